// round 2
// baseline (speedup 1.0000x reference)
#include <cuda_runtime.h>
#include <cuda_bf16.h>

// Problem constants (from reference: B=32, A=4096, P=8388608, E=8)
#define Bn 32
#define An 4096
#define NATOMS (Bn * An)

// Scratch: packed per-atom record (x, y, z, radius[elm]) — 2 MB, L2-resident.
__device__ float4 g_tab[NATOMS];
// Per-structure done bitmask: bit b set => out[b] = true (eng_big OR too_close).
__device__ unsigned g_done;

// ---------------------------------------------------------------------------
__global__ void k_init() { g_done = 0u; }

// Build atom table: fuse pos gather + elm->radius indirection into one float4.
__global__ void k_tab(const float* __restrict__ pos,
                      const int* __restrict__ elm,
                      const float* __restrict__ radius) {
    int a = blockIdx.x * blockDim.x + threadIdx.x;
    if (a < NATOMS) {
        float4 t;
        t.x = pos[3 * a + 0];
        t.y = pos[3 * a + 1];
        t.z = pos[3 * a + 2];
        t.w = __ldg(radius + elm[a]);
        g_tab[a] = t;
    }
}

// Per-structure eng_max = sum(eng_atm[elm[b,:]]); set done-bit if eng >= eng_max.
__global__ void k_engmax(const int* __restrict__ elm,
                         const float* __restrict__ eng_atm,
                         const float* __restrict__ eng) {
    __shared__ float s_atm[8];
    __shared__ float s_red[8];
    int b = blockIdx.x;
    int tid = threadIdx.x;
    if (tid < 8) s_atm[tid] = eng_atm[tid];
    __syncthreads();

    float s = 0.f;
    for (int a = tid; a < An; a += blockDim.x)
        s += s_atm[elm[b * An + a]];

    #pragma unroll
    for (int o = 16; o > 0; o >>= 1)
        s += __shfl_down_sync(0xFFFFFFFFu, s, o);
    if ((tid & 31) == 0) s_red[tid >> 5] = s;
    __syncthreads();

    if (tid == 0) {
        float tot = 0.f;
        #pragma unroll
        for (int w = 0; w < 8; ++w) tot += s_red[w];
        if (eng[b] >= tot) atomicOr(&g_done, 1u << b);
    }
}

// ---------------------------------------------------------------------------
// Pair kernel: vectorized int4 streaming of (n,i,j), 2x float4 L2 gathers per
// pair, monotone-OR done-mask with block-level early exit.
#define PT 256      // threads per block
#define PVEC 4      // pairs per thread per iteration (int4)
#define PITERS 32   // iterations per block
#define PAIRS_PER_BLOCK (PT * PVEC * PITERS)   // 32768

__global__ void __launch_bounds__(PT) k_pairs(const int* __restrict__ nn,
                                              const int* __restrict__ ii,
                                              const int* __restrict__ jj,
                                              int P) {
    __shared__ unsigned s_mask;  // block's view of the global done-mask
    __shared__ unsigned s_new;   // newly discovered bits this iteration
    int tid = threadIdx.x;
    if (tid == 0) {
        s_mask = __ldcg(&g_done);
        s_new = 0u;
    }
    __syncthreads();

    long long base = (long long)blockIdx.x * PAIRS_PER_BLOCK;

    for (int it = 0; it < PITERS; ++it) {
        unsigned m = s_mask;            // uniform across block (post-sync)
        if (m == 0xFFFFFFFFu) return;   // every structure resolved -> done

        long long idx = base + (long long)it * (PT * PVEC) + tid * PVEC;
        unsigned local = 0u;

        if (idx + PVEC <= (long long)P) {
            int4 n4 = __ldg((const int4*)(nn + idx));
            int4 i4 = __ldg((const int4*)(ii + idx));
            int4 j4 = __ldg((const int4*)(jj + idx));
            int na[4] = {n4.x, n4.y, n4.z, n4.w};
            int ia[4] = {i4.x, i4.y, i4.z, i4.w};
            int ja[4] = {j4.x, j4.y, j4.z, j4.w};
            #pragma unroll
            for (int k = 0; k < 4; ++k) {
                int nb = na[k];
                if ((m >> nb) & 1u) continue;  // structure already flagged
                float4 ta = __ldg(&g_tab[nb * An + ia[k]]);
                float4 tb = __ldg(&g_tab[nb * An + ja[k]]);
                float dx = tb.x - ta.x;
                float dy = tb.y - ta.y;
                float dz = tb.z - ta.z;
                float sod = dx * dx + dy * dy + dz * dz;
                float rs = ta.w + tb.w;
                if (rs * rs >= sod) local |= 1u << nb;
            }
        } else if (idx < (long long)P) {
            for (int k = 0; k < PVEC; ++k) {
                long long q = idx + k;
                if (q >= (long long)P) break;
                int nb = __ldg(nn + q);
                if ((m >> nb) & 1u) continue;
                float4 ta = __ldg(&g_tab[nb * An + __ldg(ii + q)]);
                float4 tb = __ldg(&g_tab[nb * An + __ldg(jj + q)]);
                float dx = tb.x - ta.x;
                float dy = tb.y - ta.y;
                float dz = tb.z - ta.z;
                float sod = dx * dx + dy * dy + dz * dz;
                float rs = ta.w + tb.w;
                if (rs * rs >= sod) local |= 1u << nb;
            }
        }

        local &= ~m;
        if (local) atomicOr(&s_new, local);
        __syncthreads();

        if (tid == 0) {
            unsigned nb2 = s_new;
            if (nb2) {
                unsigned old = atomicOr(&g_done, nb2);  // publish new bits
                s_mask = old | nb2;
                s_new = 0u;
            } else {
                s_mask = __ldcg(&g_done);               // cheap L2 poll
            }
        }
        __syncthreads();
    }
}

// Write final output as FLOAT32 (harness canonicalizes the bool reference to
// float32 — byte writes last round produced denormals ≈ 0 and rel_err = 1.0).
__global__ void k_out(float* __restrict__ out, int out_size) {
    unsigned m = g_done;
    int b = blockIdx.x * blockDim.x + threadIdx.x;
    if (b < out_size) {
        float v = (b < Bn) ? (float)((m >> b) & 1u) : 0.0f;
        out[b] = v;
    }
}

// ---------------------------------------------------------------------------
// Inputs (metadata order): pos[B,A,3] f32, eng[B] f32, elm[B,A] i32,
// radius[E] f32, eng_atm[E] f32, n[P] i32, i[P] i32, j[P] i32.
// Output: float32[B] (0.0 / 1.0).
extern "C" void kernel_launch(void* const* d_in, const int* in_sizes, int n_in,
                              void* d_out, int out_size) {
    const float* pos     = (const float*)d_in[0];
    const float* eng     = (const float*)d_in[1];
    const int*   elm     = (const int*)d_in[2];
    const float* radius  = (const float*)d_in[3];
    const float* eng_atm = (const float*)d_in[4];
    const int*   nn      = (const int*)d_in[5];
    const int*   ii      = (const int*)d_in[6];
    const int*   jj      = (const int*)d_in[7];
    int P = in_sizes[5];

    float* out = (float*)d_out;

    k_init<<<1, 1>>>();
    k_tab<<<(NATOMS + 255) / 256, 256>>>(pos, elm, radius);
    k_engmax<<<Bn, 256>>>(elm, eng_atm, eng);
    int blocks = (P + PAIRS_PER_BLOCK - 1) / PAIRS_PER_BLOCK;
    k_pairs<<<blocks, PT>>>(nn, ii, jj, P);
    k_out<<<(out_size + 31) / 32, 32>>>(out, out_size);
}